// round 10
// baseline (speedup 1.0000x reference)
#include <cuda_runtime.h>
#include <cuda_bf16.h>
#include <cstdint>
#include <math.h>

#define N 2048
#define Q 1024
#define S 512
#define NBINS 20
#define FTAB 8192

// ---------------- scratch (device globals; no allocation allowed) ----------
__device__ __nv_bfloat16 d_Ghi[(size_t)N * N];   // calibrated graph, bf16 hi
__device__ __nv_bfloat16 d_Gmid[(size_t)N * N];  // calibrated graph, bf16 mid
__device__ float d_rowsum[N];
__device__ float d_cp16[16 * N];                 // column partials (16 row-chunks)
__device__ float d_rs[N];
__device__ float d_csc[N];
__device__ float d_t[N];
__device__ float d_cw[N];
__device__ float d_ftab[FTAB + 1];
__device__ __nv_bfloat16 d_Bthi[(size_t)N * S];  // B^T gathered: [k][s], t-folded
__device__ __nv_bfloat16 d_Btmid[(size_t)N * S];
__device__ float d_gq[(size_t)Q * S];
__device__ float d_part[128 * 3];
__device__ float d_stats[3];
__device__ unsigned int d_ctr = 0;   // gemm stats counter (self-resetting)
__device__ unsigned int d_ctr2 = 0;  // colsum counter (self-resetting)

// ---------------- helpers ---------------------------------------------------
__device__ __forceinline__ uint32_t smem_u32(const void* p) {
    uint32_t a;
    asm("{ .reg .u64 t; cvta.to.shared.u64 t, %1; cvt.u32.u64 %0, t; }"
        : "=r"(a) : "l"(p));
    return a;
}
__device__ __forceinline__ void ldsm4(uint32_t (&r)[4], uint32_t addr) {
    asm volatile(
        "ldmatrix.sync.aligned.m8n8.x4.shared.b16 {%0,%1,%2,%3}, [%4];"
        : "=r"(r[0]), "=r"(r[1]), "=r"(r[2]), "=r"(r[3]) : "r"(addr));
}
__device__ __forceinline__ void ldsm4t(uint32_t (&r)[4], uint32_t addr) {
    asm volatile(
        "ldmatrix.sync.aligned.m8n8.x4.trans.shared.b16 {%0,%1,%2,%3}, [%4];"
        : "=r"(r[0]), "=r"(r[1]), "=r"(r[2]), "=r"(r[3]) : "r"(addr));
}
__device__ __forceinline__ void mma16816(float (&d)[4], const uint32_t (&a)[4],
                                         uint32_t b0, uint32_t b1) {
    asm volatile(
        "mma.sync.aligned.m16n8k16.row.col.f32.bf16.bf16.f32 "
        "{%0,%1,%2,%3}, {%4,%5,%6,%7}, {%8,%9}, {%0,%1,%2,%3};"
        : "+f"(d[0]), "+f"(d[1]), "+f"(d[2]), "+f"(d[3])
        : "r"(a[0]), "r"(a[1]), "r"(a[2]), "r"(a[3]), "r"(b0), "r"(b1));
}

// ---------------- K0: probs+table (blocks 0-15), cw softmax (block 16) ------
__global__ void k_prep(const float* __restrict__ calib_w,
                       const float* __restrict__ colw) {
    int t = threadIdx.x;
    if (blockIdx.x < 16) {
        float w[NBINS];
#pragma unroll
        for (int i = 0; i < NBINS; i++) w[i] = calib_w[i];
        float mx = w[0];
#pragma unroll
        for (int i = 1; i < NBINS; i++) mx = fmaxf(mx, w[i]);
        float e[NBINS], s = 0.f;
#pragma unroll
        for (int i = 0; i < NBINS; i++) { e[i] = expf(w[i] - mx); s += e[i]; }
        float inv = 1.0f / s;
        for (int i = blockIdx.x * 256 + t; i <= FTAB; i += 16 * 256) {
            float g = (float)i * (1.0f / FTAB);
            float zs = 0.f, zp = 0.f;
#pragma unroll
            for (int k = 0; k < NBINS; k++) {
                float d = g - (float)k * (1.0f / 19.0f);
                float z = expf(-d * d * 950.0f);
                zs += z;
                zp += z * (e[k] * inv);
            }
            d_ftab[i] = zp / zs;
        }
    } else {
        __shared__ float red[256];
        float mx = -1e30f;
        for (int j = t; j < N; j += 256) mx = fmaxf(mx, colw[j]);
        red[t] = mx; __syncthreads();
        for (int o = 128; o > 0; o >>= 1) {
            if (t < o) red[t] = fmaxf(red[t], red[t + o]);
            __syncthreads();
        }
        mx = red[0]; __syncthreads();
        float s = 0.f;
        for (int j = t; j < N; j += 256) s += expf(colw[j] - mx);
        red[t] = s; __syncthreads();
        for (int o = 128; o > 0; o >>= 1) {
            if (t < o) red[t] += red[t + o];
            __syncthreads();
        }
        float inv = (float)N / red[0];
        for (int j = t; j < N; j += 256) d_cw[j] = expf(colw[j] - mx) * inv;
    }
}

// ---------------- K1: calibration -> split bf16 + row sum (1 row / block) ---
__global__ __launch_bounds__(256) void k_calib(const float* __restrict__ graph) {
    __shared__ float red[256];
    int t = threadIdx.x;
    int row = blockIdx.x;
    const float* grow = graph + (size_t)row * N;
    __nv_bfloat16* ohi = d_Ghi + (size_t)row * N;
    __nv_bfloat16* omid = d_Gmid + (size_t)row * N;
    float rsum = 0.f;
#pragma unroll
    for (int c = 0; c < 8; c++) {
        int j = t + c * 256;
        float g = grow[j];
        float out = 0.f;
        if (g > 0.f) {
            float u = g * (float)FTAB;
            int i = min((int)u, FTAB - 1);
            float fr = u - (float)i;
            float f0 = d_ftab[i], f1 = d_ftab[i + 1];   // L1/L2-resident table
            out = f0 + fr * (f1 - f0);
        }
        __nv_bfloat16 hi = __float2bfloat16(out);
        ohi[j] = hi;
        omid[j] = __float2bfloat16(out - __bfloat162float(hi));
        rsum += out;
    }
    red[t] = rsum; __syncthreads();
    for (int o = 128; o > 0; o >>= 1) {
        if (t < o) red[t] += red[t + o];
        __syncthreads();
    }
    if (t == 0) d_rowsum[row] = red[0];
}

// ---------------- K2: column partials + fused scales (last-block) -----------
// grid (8,16): block (x,y) sums rows [y*128, y*128+128) for cols x*256..+255.
// Last-arriving block reduces the 16 partials and writes rs/csc/t.
__global__ __launch_bounds__(256) void k_colsum_scales() {
    int t = threadIdx.x;
    int j = blockIdx.x * 256 + t;
    int r0 = blockIdx.y * 128;
    float s = 0.f;
#pragma unroll 4
    for (int r = 0; r < 128; r++) {
        size_t idx = (size_t)(r0 + r) * N + j;
        s += __bfloat162float(d_Ghi[idx]) + __bfloat162float(d_Gmid[idx]);
    }
    d_cp16[blockIdx.y * N + j] = s;

    __shared__ unsigned int is_last;
    __threadfence();
    if (t == 0) {
        unsigned int old = atomicAdd(&d_ctr2, 1u);
        is_last = (old == 127u) ? 1u : 0u;
    }
    __syncthreads();
    if (is_last) {
        __threadfence();
        for (int jj = t; jj < N; jj += 256) {
            float cs = 0.f;
#pragma unroll
            for (int p = 0; p < 16; p++) cs += d_cp16[p * N + jj];
            float rsum = d_rowsum[jj];
            float rs = (rsum > 0.f) ? rsqrtf(rsum) : 0.f;
            float cc = (cs > 0.f) ? rsqrtf(cs) : 0.f;
            float csc = cc * d_cw[jj];
            d_rs[jj] = rs;
            d_csc[jj] = csc;
            d_t[jj] = rs * csc;
        }
        if (t == 0) d_ctr2 = 0;   // reset for next graph replay
    }
}

// ---------------- K3: B gather, 4 k-rows per block, deep MLP ----------------
__global__ __launch_bounds__(256) void k_gatherB(const int* __restrict__ sid) {
    int t = threadIdx.x;
    int k0 = blockIdx.x * 4;
    int c0 = sid[t], c1 = sid[t + 256];
    float h[4][2], m[4][2], tk[4];
#pragma unroll
    for (int r = 0; r < 4; r++) {
        const __nv_bfloat16* gh = d_Ghi + (size_t)(k0 + r) * N;
        const __nv_bfloat16* gm = d_Gmid + (size_t)(k0 + r) * N;
        h[r][0] = __bfloat162float(gh[c0]);
        h[r][1] = __bfloat162float(gh[c1]);
        m[r][0] = __bfloat162float(gm[c0]);
        m[r][1] = __bfloat162float(gm[c1]);
        tk[r] = d_t[k0 + r];
    }
#pragma unroll
    for (int r = 0; r < 4; r++) {
        int k = k0 + r;
        float v0 = (h[r][0] + m[r][0]) * tk[r];
        float v1 = (h[r][1] + m[r][1]) * tk[r];
        __nv_bfloat16 hi0 = __float2bfloat16(v0);
        __nv_bfloat16 hi1 = __float2bfloat16(v1);
        d_Bthi[(size_t)k * S + t] = hi0;
        d_Bthi[(size_t)k * S + t + 256] = hi1;
        d_Btmid[(size_t)k * S + t] = __float2bfloat16(v0 - __bfloat162float(hi0));
        d_Btmid[(size_t)k * S + t + 256] = __float2bfloat16(v1 - __bfloat162float(hi1));
    }
}

// ---------------- K4: HMMA GEMM + epilogue + fused stats --------------------
#define TILE_BYTES 16384
__global__ __launch_bounds__(256) void k_gemm_mma(const int* __restrict__ qid,
                                                  const int* __restrict__ sid) {
    __shared__ __align__(128) char sm[2 * TILE_BYTES];
    int tid = threadIdx.x, lane = tid & 31, wid = tid >> 5;
    int bx = blockIdx.x, by = blockIdx.y;
    uint32_t sb = smem_u32(sm);

    int lr = tid >> 2;
    int lc = (tid & 3) * 16;
    uint32_t lswA = (uint32_t)(lr * 64 + lc) ^ ((uint32_t)(lr & 7) << 4);
    int aRow = qid[by * 64 + lr];
    const char* pAh = (const char*)d_Ghi  + (size_t)aRow * 4096 + lc;
    const char* pAm = (const char*)d_Gmid + (size_t)aRow * 4096 + lc;
    int lrB = tid >> 3;
    int lcB = (tid & 7) * 16;
    uint32_t lswB = (uint32_t)(lrB * 128 + lcB) ^ ((uint32_t)(lrB & 7) << 4);
    const char* pBh = (const char*)d_Bthi  + (size_t)lrB * 1024 + bx * 128 + lcB;
    const char* pBm = (const char*)d_Btmid + (size_t)lrB * 1024 + bx * 128 + lcB;

    float acc[2][2][4];
#pragma unroll
    for (int i = 0; i < 2; i++)
#pragma unroll
        for (int j = 0; j < 2; j++)
#pragma unroll
            for (int k = 0; k < 4; k++) acc[i][j][k] = 0.f;

    int wm = wid & 1, wn = wid >> 1;

    uint4 ra, rb, rc, rd;
    ra = *(const uint4*)(pAh); rb = *(const uint4*)(pAm);
    rc = *(const uint4*)(pBh); rd = *(const uint4*)(pBm);
    *(uint4*)(sm + lswA)         = ra;
    *(uint4*)(sm + 4096 + lswA)  = rb;
    *(uint4*)(sm + 8192 + lswB)  = rc;
    *(uint4*)(sm + 12288 + lswB) = rd;

    for (int kb = 0; kb < 64; kb++) {
        int b = kb & 1;
        if (kb < 63) {
            int oA = (kb + 1) * 64;
            int oB = (kb + 1) * 32768;
            ra = *(const uint4*)(pAh + oA); rb = *(const uint4*)(pAm + oA);
            rc = *(const uint4*)(pBh + oB); rd = *(const uint4*)(pBm + oB);
        }
        __syncthreads();
        uint32_t base = sb + b * TILE_BYTES;

        uint32_t bh[2][4], bm[2][4];
#pragma unroll
        for (int ni = 0; ni < 2; ni++) {
            uint32_t off = (uint32_t)(lane * 128 + wn * 32 + ni * 16);
            uint32_t sw = off ^ ((uint32_t)(lane & 7) << 4);
            ldsm4t(bh[ni], base + 8192 + sw);
            ldsm4t(bm[ni], base + 12288 + sw);
        }
#pragma unroll
        for (int k16 = 0; k16 < 2; k16++) {
            uint32_t ah[2][4], am[2][4];
#pragma unroll
            for (int mi = 0; mi < 2; mi++) {
                int row = wm * 32 + mi * 16 + (lane & 15);
                uint32_t off = (uint32_t)(row * 64 + k16 * 32 + ((lane >> 4) * 16));
                uint32_t sw = off ^ ((uint32_t)(row & 7) << 4);
                ldsm4(ah[mi], base + sw);
                ldsm4(am[mi], base + 4096 + sw);
            }
#pragma unroll
            for (int mi = 0; mi < 2; mi++)
#pragma unroll
                for (int ni = 0; ni < 2; ni++) {
                    mma16816(acc[mi][ni], ah[mi], bh[ni][k16 * 2], bh[ni][k16 * 2 + 1]);
                    mma16816(acc[mi][ni], ah[mi], bm[ni][k16 * 2], bm[ni][k16 * 2 + 1]);
                    mma16816(acc[mi][ni], am[mi], bh[ni][k16 * 2], bh[ni][k16 * 2 + 1]);
                }
        }
        if (kb < 63) {
            char* so = sm + (1 - b) * TILE_BYTES;
            *(uint4*)(so + lswA)         = ra;
            *(uint4*)(so + 4096 + lswA)  = rb;
            *(uint4*)(so + 8192 + lswB)  = rc;
            *(uint4*)(so + 12288 + lswB) = rd;
        }
    }

    int c0 = bx * 64 + wn * 16 + (lane & 3) * 2;
    int sdA0 = sid[c0], sdA1 = sid[c0 + 1];
    int sdB0 = sid[c0 + 8], sdB1 = sid[c0 + 9];
    float csA0 = d_csc[sdA0], csA1 = d_csc[sdA1];
    float csB0 = d_csc[sdB0], csB1 = d_csc[sdB1];

    float pc = 0.f, ps = 0.f, pq2 = 0.f;
#pragma unroll
    for (int mi = 0; mi < 2; mi++) {
        int r0 = by * 64 + wm * 32 + mi * 16 + (lane >> 2);
#pragma unroll
        for (int half = 0; half < 2; half++) {
            int r = r0 + half * 8;
            int qq = qid[r];
            float rq = d_rs[qq];
            {
                float v0 = acc[mi][0][half * 2 + 0] * rq * csA0;
                float v1 = acc[mi][0][half * 2 + 1] * rq * csA1;
                if (sdA0 == qq) v0 = 0.f;
                if (sdA1 == qq) v1 = 0.f;
                *(float2*)&d_gq[(size_t)r * S + c0] = make_float2(v0, v1);
                if (v0 > 0.f) pc += 1.f;
                if (v1 > 0.f) pc += 1.f;
                ps += v0 + v1;
                pq2 += v0 * v0 + v1 * v1;
            }
            {
                float v0 = acc[mi][1][half * 2 + 0] * rq * csB0;
                float v1 = acc[mi][1][half * 2 + 1] * rq * csB1;
                if (sdB0 == qq) v0 = 0.f;
                if (sdB1 == qq) v1 = 0.f;
                *(float2*)&d_gq[(size_t)r * S + c0 + 8] = make_float2(v0, v1);
                if (v0 > 0.f) pc += 1.f;
                if (v1 > 0.f) pc += 1.f;
                ps += v0 + v1;
                pq2 += v0 * v0 + v1 * v1;
            }
        }
    }
    __syncthreads();
    float* r0s = (float*)sm;
    float* r1s = r0s + 256;
    float* r2s = r1s + 256;
    r0s[tid] = pc; r1s[tid] = ps; r2s[tid] = pq2;
    __syncthreads();
    for (int o = 128; o > 0; o >>= 1) {
        if (tid < o) {
            r0s[tid] += r0s[tid + o];
            r1s[tid] += r1s[tid + o];
            r2s[tid] += r2s[tid + o];
        }
        __syncthreads();
    }
    int cta = by * 8 + bx;
    if (tid == 0) {
        d_part[cta * 3 + 0] = r0s[0];
        d_part[cta * 3 + 1] = r1s[0];
        d_part[cta * 3 + 2] = r2s[0];
    }
    __shared__ unsigned int is_last;
    __threadfence();
    if (tid == 0) {
        unsigned int old = atomicAdd(&d_ctr, 1u);
        is_last = (old == 127u) ? 1u : 0u;
    }
    __syncthreads();
    if (is_last) {
        __threadfence();
        float a0 = 0.f, a1 = 0.f, a2 = 0.f;
        if (tid < 128) {
            a0 = d_part[tid * 3 + 0];
            a1 = d_part[tid * 3 + 1];
            a2 = d_part[tid * 3 + 2];
        }
        r0s[tid] = a0; r1s[tid] = a1; r2s[tid] = a2;
        __syncthreads();
        for (int o = 64; o > 0; o >>= 1) {
            if (tid < o) {
                r0s[tid] += r0s[tid + o];
                r1s[tid] += r1s[tid + o];
                r2s[tid] += r2s[tid + o];
            }
            __syncthreads();
        }
        if (tid == 0) {
            d_stats[0] = r0s[0];
            d_stats[1] = r1s[0];
            d_stats[2] = r2s[0];
            d_ctr = 0;
        }
    }
}

// ---------------- K5: standardize, powers, ELU, row-normalize ---------------
__global__ void k_final(const float* __restrict__ gw,
                        const float* __restrict__ gb,
                        float* __restrict__ out) {
    int q = blockIdx.x, t = threadIdx.x;
    __shared__ float red[256];
    float s0 = d_stats[0], s1 = d_stats[1], s2 = d_stats[2];
    float mean = s1 / s0;
    float var = fmaxf(s2 / s0 - mean * mean, 1e-30f);
    float istd = rsqrtf(var);
    float w0 = gw[0], w1 = gw[1], w2 = gw[2], w3 = gw[3], w4 = gw[4];
    float b = gb[0];

    float y[2];
#pragma unroll
    for (int c = 0; c < 2; c++) {
        float g = d_gq[(size_t)q * S + t + c * 256];
        float yy = 0.f;
        if (g > 0.f) {
            float x = (g - mean) * istd;
            float m = fabsf(x);
            float sq = (m > 0.f) ? copysignf(sqrtf(m), x) : 0.f;
            float xm = x * m;
            float p = b + w0 * x + w1 * sq + w2 * xm + w3 * xm * m + w4 * xm * m * m;
            yy = ((p > 0.f) ? p : expm1f(p)) + 1.f;
        }
        y[c] = yy;
    }
    red[t] = y[0] + y[1];
    __syncthreads();
    for (int o = 128; o > 0; o >>= 1) {
        if (t < o) red[t] += red[t + o];
        __syncthreads();
    }
    float tot = red[0];
    float inv = (tot != 0.f) ? 1.0f / tot : 0.f;
    out[(size_t)q * S + t] = y[0] * inv;
    out[(size_t)q * S + t + 256] = y[1] * inv;
}

// ---------------- launch ----------------------------------------------------
extern "C" void kernel_launch(void* const* d_in, const int* in_sizes, int n_in,
                              void* d_out, int out_size) {
    const float* graph    = (const float*)d_in[0];
    const float* calib_w  = (const float*)d_in[1];
    const float* global_w = (const float*)d_in[2];
    const float* global_b = (const float*)d_in[3];
    const float* col_w    = (const float*)d_in[4];
    const int*   qid      = (const int*)d_in[5];
    const int*   sid      = (const int*)d_in[6];
    float* out = (float*)d_out;

    k_prep<<<17, 256>>>(calib_w, col_w);
    k_calib<<<N, 256>>>(graph);
    k_colsum_scales<<<dim3(8, 16), 256>>>();
    k_gatherB<<<512, 256>>>(sid);
    k_gemm_mma<<<dim3(8, 16), 256>>>(qid, sid);
    k_final<<<Q, 256>>>(global_w, global_b, out);
}

// round 11
// speedup vs baseline: 1.1140x; 1.1140x over previous
#include <cuda_runtime.h>
#include <cuda_bf16.h>
#include <cstdint>
#include <math.h>

#define N 2048
#define Q 1024
#define S 512
#define NBINS 20
#define FTAB 8192

// ---------------- scratch (device globals; no allocation allowed) ----------
__device__ __nv_bfloat16 d_Ghi[(size_t)N * N];   // calibrated graph, bf16 hi
__device__ __nv_bfloat16 d_Gmid[(size_t)N * N];  // calibrated graph, bf16 mid
__device__ float d_rowsum[N];
__device__ float d_cp[256 * N];                  // per-calib-block column partials
__device__ float d_rs[N];
__device__ float d_csc[N];
__device__ float d_t[N];
__device__ float d_cw[N];
__device__ float d_ftab[FTAB + 1];
__device__ __nv_bfloat162 d_Bt0[(size_t)N * S];  // unscaled gathered B: [k][s] packed (hi,mid)
__device__ __nv_bfloat16 d_Bthi[(size_t)N * S];  // B^T scaled: [k][s]
__device__ __nv_bfloat16 d_Btmid[(size_t)N * S];
__device__ float d_gq[(size_t)Q * S];
__device__ float d_part[128 * 3];
__device__ float d_stats[3];
__device__ unsigned int d_ctr = 0;

// ---------------- helpers ---------------------------------------------------
__device__ __forceinline__ uint32_t smem_u32(const void* p) {
    uint32_t a;
    asm("{ .reg .u64 t; cvta.to.shared.u64 t, %1; cvt.u32.u64 %0, t; }"
        : "=r"(a) : "l"(p));
    return a;
}
__device__ __forceinline__ void ldsm4(uint32_t (&r)[4], uint32_t addr) {
    asm volatile(
        "ldmatrix.sync.aligned.m8n8.x4.shared.b16 {%0,%1,%2,%3}, [%4];"
        : "=r"(r[0]), "=r"(r[1]), "=r"(r[2]), "=r"(r[3]) : "r"(addr));
}
__device__ __forceinline__ void ldsm4t(uint32_t (&r)[4], uint32_t addr) {
    asm volatile(
        "ldmatrix.sync.aligned.m8n8.x4.trans.shared.b16 {%0,%1,%2,%3}, [%4];"
        : "=r"(r[0]), "=r"(r[1]), "=r"(r[2]), "=r"(r[3]) : "r"(addr));
}
__device__ __forceinline__ void mma16816(float (&d)[4], const uint32_t (&a)[4],
                                         uint32_t b0, uint32_t b1) {
    asm volatile(
        "mma.sync.aligned.m16n8k16.row.col.f32.bf16.bf16.f32 "
        "{%0,%1,%2,%3}, {%4,%5,%6,%7}, {%8,%9}, {%0,%1,%2,%3};"
        : "+f"(d[0]), "+f"(d[1]), "+f"(d[2]), "+f"(d[3])
        : "r"(a[0]), "r"(a[1]), "r"(a[2]), "r"(a[3]), "r"(b0), "r"(b1));
}

// ---------------- K0: probs+table (blocks 0-15), cw softmax (block 16) ------
__global__ void k_prep(const float* __restrict__ calib_w,
                       const float* __restrict__ colw) {
    int t = threadIdx.x;
    if (blockIdx.x < 16) {
        float w[NBINS];
#pragma unroll
        for (int i = 0; i < NBINS; i++) w[i] = calib_w[i];
        float mx = w[0];
#pragma unroll
        for (int i = 1; i < NBINS; i++) mx = fmaxf(mx, w[i]);
        float e[NBINS], s = 0.f;
#pragma unroll
        for (int i = 0; i < NBINS; i++) { e[i] = expf(w[i] - mx); s += e[i]; }
        float inv = 1.0f / s;
        for (int i = blockIdx.x * 256 + t; i <= FTAB; i += 16 * 256) {
            float g = (float)i * (1.0f / FTAB);
            float zs = 0.f, zp = 0.f;
#pragma unroll
            for (int k = 0; k < NBINS; k++) {
                float d = g - (float)k * (1.0f / 19.0f);
                float z = expf(-d * d * 950.0f);
                zs += z;
                zp += z * (e[k] * inv);
            }
            d_ftab[i] = zp / zs;
        }
    } else {
        __shared__ float red[256];
        float mx = -1e30f;
        for (int j = t; j < N; j += 256) mx = fmaxf(mx, colw[j]);
        red[t] = mx; __syncthreads();
        for (int o = 128; o > 0; o >>= 1) {
            if (t < o) red[t] = fmaxf(red[t], red[t + o]);
            __syncthreads();
        }
        mx = red[0]; __syncthreads();
        float s = 0.f;
        for (int j = t; j < N; j += 256) s += expf(colw[j] - mx);
        red[t] = s; __syncthreads();
        for (int o = 128; o > 0; o >>= 1) {
            if (t < o) red[t] += red[t + o];
            __syncthreads();
        }
        float inv = (float)N / red[0];
        for (int j = t; j < N; j += 256) d_cw[j] = expf(colw[j] - mx) * inv;
    }
}

// ---------------- K1: calibration -> split bf16, row sums, column partials,
//                     + in-register seed gather (unscaled, packed) ----------
__global__ __launch_bounds__(256) void k_calib(const float* __restrict__ graph,
                                               const int* __restrict__ sid) {
    __shared__ float tab[FTAB + 1];
    __shared__ float red[256];
    __shared__ float srow[N];
    __shared__ int ss[S];
    int t = threadIdx.x;
    for (int i = t; i <= FTAB; i += 256) tab[i] = d_ftab[i];
    ss[t] = sid[t];
    ss[t + 256] = sid[t + 256];
    __syncthreads();
    int row0 = blockIdx.x * 8;
    float colacc[8] = {0.f, 0.f, 0.f, 0.f, 0.f, 0.f, 0.f, 0.f};
    for (int r = 0; r < 8; r++) {
        int row = row0 + r;
        const float* grow = graph + (size_t)row * N;
        __nv_bfloat16* ohi = d_Ghi + (size_t)row * N;
        __nv_bfloat16* omid = d_Gmid + (size_t)row * N;
        float rsum = 0.f;
#pragma unroll
        for (int c = 0; c < 8; c++) {
            int j = t + c * 256;
            float g = grow[j];
            float out = 0.f;
            if (g > 0.f) {
                float u = g * (float)FTAB;
                int i = min((int)u, FTAB - 1);
                float fr = u - (float)i;
                float f0 = tab[i], f1 = tab[i + 1];
                out = f0 + fr * (f1 - f0);
            }
            __nv_bfloat16 hi = __float2bfloat16(out);
            ohi[j] = hi;
            omid[j] = __float2bfloat16(out - __bfloat162float(hi));
            srow[j] = out;
            rsum += out;
            colacc[c] += out;
        }
        red[t] = rsum; __syncthreads();   // also publishes srow
        for (int o = 128; o > 0; o >>= 1) {
            if (t < o) red[t] += red[t + o];
            __syncthreads();
        }
        if (t == 0) d_rowsum[row] = red[0];
        // gather 512 seed columns of this row from smem, unscaled, packed
#pragma unroll
        for (int c2 = 0; c2 < 2; c2++) {
            int s = t + c2 * 256;
            float v = srow[ss[s]];
            __nv_bfloat16 hi = __float2bfloat16(v);
            __nv_bfloat162 pk;
            pk.x = hi;
            pk.y = __float2bfloat16(v - __bfloat162float(hi));
            d_Bt0[(size_t)row * S + s] = pk;
        }
        __syncthreads();   // protect srow before next row overwrites it
    }
#pragma unroll
    for (int c = 0; c < 8; c++)
        d_cp[blockIdx.x * N + t + c * 256] = colacc[c];
}

// ---------------- K2: column sums + per-index scales ------------------------
__global__ void k_colsum_scales() {
    int j = blockIdx.x * 256 + threadIdx.x;
    float cs = 0.f;
#pragma unroll 8
    for (int p = 0; p < 256; p++) cs += d_cp[p * N + j];
    float rsum = d_rowsum[j];
    float rs = (rsum > 0.f) ? rsqrtf(rsum) : 0.f;
    float cc = (cs > 0.f) ? rsqrtf(cs) : 0.f;
    float csc = cc * d_cw[j];
    d_rs[j] = rs;
    d_csc[j] = csc;
    d_t[j] = rs * csc;
}

// ---------------- K3: scale B rows by t[k], re-split (pure streaming) -------
__global__ __launch_bounds__(256) void k_scaleB() {
    int t = threadIdx.x;
    int k = blockIdx.x;
    float tk = d_t[k];
#pragma unroll
    for (int c = 0; c < 2; c++) {
        int s = t + c * 256;
        __nv_bfloat162 p = d_Bt0[(size_t)k * S + s];
        float v = (__bfloat162float(p.x) + __bfloat162float(p.y)) * tk;
        __nv_bfloat16 hi = __float2bfloat16(v);
        d_Bthi[(size_t)k * S + s] = hi;
        d_Btmid[(size_t)k * S + s] = __float2bfloat16(v - __bfloat162float(hi));
    }
}

// ---------------- K4: HMMA GEMM + epilogue + fused stats --------------------
#define TILE_BYTES 16384
__global__ __launch_bounds__(256) void k_gemm_mma(const int* __restrict__ qid,
                                                  const int* __restrict__ sid) {
    __shared__ __align__(128) char sm[2 * TILE_BYTES];
    int tid = threadIdx.x, lane = tid & 31, wid = tid >> 5;
    int bx = blockIdx.x, by = blockIdx.y;
    uint32_t sb = smem_u32(sm);

    int lr = tid >> 2;
    int lc = (tid & 3) * 16;
    uint32_t lswA = (uint32_t)(lr * 64 + lc) ^ ((uint32_t)(lr & 7) << 4);
    int aRow = qid[by * 64 + lr];
    const char* pAh = (const char*)d_Ghi  + (size_t)aRow * 4096 + lc;
    const char* pAm = (const char*)d_Gmid + (size_t)aRow * 4096 + lc;
    int lrB = tid >> 3;
    int lcB = (tid & 7) * 16;
    uint32_t lswB = (uint32_t)(lrB * 128 + lcB) ^ ((uint32_t)(lrB & 7) << 4);
    const char* pBh = (const char*)d_Bthi  + (size_t)lrB * 1024 + bx * 128 + lcB;
    const char* pBm = (const char*)d_Btmid + (size_t)lrB * 1024 + bx * 128 + lcB;

    float acc[2][2][4];
#pragma unroll
    for (int i = 0; i < 2; i++)
#pragma unroll
        for (int j = 0; j < 2; j++)
#pragma unroll
            for (int k = 0; k < 4; k++) acc[i][j][k] = 0.f;

    int wm = wid & 1, wn = wid >> 1;

    uint4 ra, rb, rc, rd;
    ra = *(const uint4*)(pAh); rb = *(const uint4*)(pAm);
    rc = *(const uint4*)(pBh); rd = *(const uint4*)(pBm);
    *(uint4*)(sm + lswA)         = ra;
    *(uint4*)(sm + 4096 + lswA)  = rb;
    *(uint4*)(sm + 8192 + lswB)  = rc;
    *(uint4*)(sm + 12288 + lswB) = rd;

    for (int kb = 0; kb < 64; kb++) {
        int b = kb & 1;
        if (kb < 63) {
            int oA = (kb + 1) * 64;
            int oB = (kb + 1) * 32768;
            ra = *(const uint4*)(pAh + oA); rb = *(const uint4*)(pAm + oA);
            rc = *(const uint4*)(pBh + oB); rd = *(const uint4*)(pBm + oB);
        }
        __syncthreads();
        uint32_t base = sb + b * TILE_BYTES;

        uint32_t bh[2][4], bm[2][4];
#pragma unroll
        for (int ni = 0; ni < 2; ni++) {
            uint32_t off = (uint32_t)(lane * 128 + wn * 32 + ni * 16);
            uint32_t sw = off ^ ((uint32_t)(lane & 7) << 4);
            ldsm4t(bh[ni], base + 8192 + sw);
            ldsm4t(bm[ni], base + 12288 + sw);
        }
#pragma unroll
        for (int k16 = 0; k16 < 2; k16++) {
            uint32_t ah[2][4], am[2][4];
#pragma unroll
            for (int mi = 0; mi < 2; mi++) {
                int row = wm * 32 + mi * 16 + (lane & 15);
                uint32_t off = (uint32_t)(row * 64 + k16 * 32 + ((lane >> 4) * 16));
                uint32_t sw = off ^ ((uint32_t)(row & 7) << 4);
                ldsm4(ah[mi], base + sw);
                ldsm4(am[mi], base + 4096 + sw);
            }
#pragma unroll
            for (int mi = 0; mi < 2; mi++)
#pragma unroll
                for (int ni = 0; ni < 2; ni++) {
                    mma16816(acc[mi][ni], ah[mi], bh[ni][k16 * 2], bh[ni][k16 * 2 + 1]);
                    mma16816(acc[mi][ni], ah[mi], bm[ni][k16 * 2], bm[ni][k16 * 2 + 1]);
                    mma16816(acc[mi][ni], am[mi], bh[ni][k16 * 2], bh[ni][k16 * 2 + 1]);
                }
        }
        if (kb < 63) {
            char* so = sm + (1 - b) * TILE_BYTES;
            *(uint4*)(so + lswA)         = ra;
            *(uint4*)(so + 4096 + lswA)  = rb;
            *(uint4*)(so + 8192 + lswB)  = rc;
            *(uint4*)(so + 12288 + lswB) = rd;
        }
    }

    int c0 = bx * 64 + wn * 16 + (lane & 3) * 2;
    int sdA0 = sid[c0], sdA1 = sid[c0 + 1];
    int sdB0 = sid[c0 + 8], sdB1 = sid[c0 + 9];
    float csA0 = d_csc[sdA0], csA1 = d_csc[sdA1];
    float csB0 = d_csc[sdB0], csB1 = d_csc[sdB1];

    float pc = 0.f, ps = 0.f, pq2 = 0.f;
#pragma unroll
    for (int mi = 0; mi < 2; mi++) {
        int r0 = by * 64 + wm * 32 + mi * 16 + (lane >> 2);
#pragma unroll
        for (int half = 0; half < 2; half++) {
            int r = r0 + half * 8;
            int qq = qid[r];
            float rq = d_rs[qq];
            {
                float v0 = acc[mi][0][half * 2 + 0] * rq * csA0;
                float v1 = acc[mi][0][half * 2 + 1] * rq * csA1;
                if (sdA0 == qq) v0 = 0.f;
                if (sdA1 == qq) v1 = 0.f;
                *(float2*)&d_gq[(size_t)r * S + c0] = make_float2(v0, v1);
                if (v0 > 0.f) pc += 1.f;
                if (v1 > 0.f) pc += 1.f;
                ps += v0 + v1;
                pq2 += v0 * v0 + v1 * v1;
            }
            {
                float v0 = acc[mi][1][half * 2 + 0] * rq * csB0;
                float v1 = acc[mi][1][half * 2 + 1] * rq * csB1;
                if (sdB0 == qq) v0 = 0.f;
                if (sdB1 == qq) v1 = 0.f;
                *(float2*)&d_gq[(size_t)r * S + c0 + 8] = make_float2(v0, v1);
                if (v0 > 0.f) pc += 1.f;
                if (v1 > 0.f) pc += 1.f;
                ps += v0 + v1;
                pq2 += v0 * v0 + v1 * v1;
            }
        }
    }
    __syncthreads();
    float* r0s = (float*)sm;
    float* r1s = r0s + 256;
    float* r2s = r1s + 256;
    r0s[tid] = pc; r1s[tid] = ps; r2s[tid] = pq2;
    __syncthreads();
    for (int o = 128; o > 0; o >>= 1) {
        if (tid < o) {
            r0s[tid] += r0s[tid + o];
            r1s[tid] += r1s[tid + o];
            r2s[tid] += r2s[tid + o];
        }
        __syncthreads();
    }
    int cta = by * 8 + bx;
    if (tid == 0) {
        d_part[cta * 3 + 0] = r0s[0];
        d_part[cta * 3 + 1] = r1s[0];
        d_part[cta * 3 + 2] = r2s[0];
    }
    __shared__ unsigned int is_last;
    __threadfence();
    if (tid == 0) {
        unsigned int old = atomicAdd(&d_ctr, 1u);
        is_last = (old == 127u) ? 1u : 0u;
    }
    __syncthreads();
    if (is_last) {
        __threadfence();
        float a0 = 0.f, a1 = 0.f, a2 = 0.f;
        if (tid < 128) {
            a0 = d_part[tid * 3 + 0];
            a1 = d_part[tid * 3 + 1];
            a2 = d_part[tid * 3 + 2];
        }
        r0s[tid] = a0; r1s[tid] = a1; r2s[tid] = a2;
        __syncthreads();
        for (int o = 64; o > 0; o >>= 1) {
            if (tid < o) {
                r0s[tid] += r0s[tid + o];
                r1s[tid] += r1s[tid + o];
                r2s[tid] += r2s[tid + o];
            }
            __syncthreads();
        }
        if (tid == 0) {
            d_stats[0] = r0s[0];
            d_stats[1] = r1s[0];
            d_stats[2] = r2s[0];
            d_ctr = 0;
        }
    }
}

// ---------------- K5: standardize, powers, ELU, row-normalize ---------------
__global__ void k_final(const float* __restrict__ gw,
                        const float* __restrict__ gb,
                        float* __restrict__ out) {
    int q = blockIdx.x, t = threadIdx.x;
    __shared__ float red[256];
    float s0 = d_stats[0], s1 = d_stats[1], s2 = d_stats[2];
    float mean = s1 / s0;
    float var = fmaxf(s2 / s0 - mean * mean, 1e-30f);
    float istd = rsqrtf(var);
    float w0 = gw[0], w1 = gw[1], w2 = gw[2], w3 = gw[3], w4 = gw[4];
    float b = gb[0];

    float y[2];
#pragma unroll
    for (int c = 0; c < 2; c++) {
        float g = d_gq[(size_t)q * S + t + c * 256];
        float yy = 0.f;
        if (g > 0.f) {
            float x = (g - mean) * istd;
            float m = fabsf(x);
            float sq = (m > 0.f) ? copysignf(sqrtf(m), x) : 0.f;
            float xm = x * m;
            float p = b + w0 * x + w1 * sq + w2 * xm + w3 * xm * m + w4 * xm * m * m;
            yy = ((p > 0.f) ? p : expm1f(p)) + 1.f;
        }
        y[c] = yy;
    }
    red[t] = y[0] + y[1];
    __syncthreads();
    for (int o = 128; o > 0; o >>= 1) {
        if (t < o) red[t] += red[t + o];
        __syncthreads();
    }
    float tot = red[0];
    float inv = (tot != 0.f) ? 1.0f / tot : 0.f;
    out[(size_t)q * S + t] = y[0] * inv;
    out[(size_t)q * S + t + 256] = y[1] * inv;
}

// ---------------- launch ----------------------------------------------------
extern "C" void kernel_launch(void* const* d_in, const int* in_sizes, int n_in,
                              void* d_out, int out_size) {
    const float* graph    = (const float*)d_in[0];
    const float* calib_w  = (const float*)d_in[1];
    const float* global_w = (const float*)d_in[2];
    const float* global_b = (const float*)d_in[3];
    const float* col_w    = (const float*)d_in[4];
    const int*   qid      = (const int*)d_in[5];
    const int*   sid      = (const int*)d_in[6];
    float* out = (float*)d_out;

    k_prep<<<17, 256>>>(calib_w, col_w);
    k_calib<<<256, 256>>>(graph, sid);
    k_colsum_scales<<<8, 256>>>();
    k_scaleB<<<N, 256>>>();
    k_gemm_mma<<<dim3(8, 16), 256>>>(qid, sid);
    k_final<<<Q, 256>>>(global_w, global_b, out);
}